// round 12
// baseline (speedup 1.0000x reference)
#include <cuda_runtime.h>
#include <stdint.h>

// Problem constants
#define NUM_COORDS   200000
#define FEAT_C       128
#define MAX_SELECTED 262144
#define N_ELEMS      (512 * NUM_COORDS)         // 102,400,000 mask elements
#define THREADS      512
#define ELEMS_PER_TH 16
#define ELEMS_PER_BLK (THREADS * ELEMS_PER_TH)  // 8192
#define NBLK         (N_ELEMS / ELEMS_PER_BLK)  // 12500 exactly
#define NWARP        (THREADS / 32)             // 16
#define QCAP         1024                       // smem queue capacity (rows)

// Decoupled-lookback descriptor: bits 31:30 flag, bits 29:0 value.
#define FLAG_INVALID 0u
#define FLAG_AGG     (1u << 30)
#define FLAG_PREFIX  (2u << 30)
#define VAL_MASK     0x3FFFFFFFu

// Scratch. g_desc starts zero (INVALID); k_tail resets it after every fused
// run so each graph replay sees a clean state.
__device__ unsigned g_desc[NBLK];
__device__ int g_count;
__device__ unsigned g_nonconform = 0;  // 1 => byte-bools; 0 => 32-bit elems

// ---------------------------------------------------------------------------
// Mode detection (256K-word scan). Word-mode masks contain only
// {0,1,0x3F800000}. Monotone + input-determined => replay-safe without reset.
// ---------------------------------------------------------------------------
__global__ void k_detect(const unsigned* __restrict__ w) {
    unsigned i = blockIdx.x * blockDim.x + threadIdx.x;
    unsigned bad = 0;
    for (unsigned j = i; j < (1u << 18); j += gridDim.x * blockDim.x) {
        unsigned v = w[j];
        if (v != 0u && v != 1u && v != 0x3F800000u) bad = 1u;
    }
    if (bad) g_nonconform = 1u;
}

// Load this thread's 16 contiguous elements; return count of set elements.
__device__ __forceinline__ int load_count(const void* mask, int blk, int tid,
                                          int byte_mode, uint4 v[4]) {
    if (byte_mode) {
        v[0] = ((const uint4*)mask)[(size_t)blk * (ELEMS_PER_BLK / 16) + tid];
        unsigned a = 0;
        a = __dp4a(v[0].x, 0x01010101u, a);
        a = __dp4a(v[0].y, 0x01010101u, a);
        a = __dp4a(v[0].z, 0x01010101u, a);
        a = __dp4a(v[0].w, 0x01010101u, a);
        return (int)a;
    } else {
        const uint4* p = (const uint4*)mask + (size_t)blk * (ELEMS_PER_BLK / 4)
                         + (size_t)tid * 4;
        int c = 0;
#pragma unroll
        for (int i = 0; i < 4; i++) {
            v[i] = p[i];
            c += (v[i].x != 0u) + (v[i].y != 0u) + (v[i].z != 0u) + (v[i].w != 0u);
        }
        return c;
    }
}

// ---------------------------------------------------------------------------
// Fused single-pass: block scan + warp-0 decoupled lookback (atomicAdd
// polling, 32-window — the proven R6 mechanism) + ordered ext emit +
// WARP-COOPERATIVE feature copy via smem queue.
// ---------------------------------------------------------------------------
__global__ void __launch_bounds__(THREADS)
k_fused(const void* __restrict__ mask,
        const int4* __restrict__ coords,
        const float4* __restrict__ feat,
        float4* __restrict__ out_ext,
        float4* __restrict__ out_feat) {
    const int blk = blockIdx.x, tid = threadIdx.x;
    const int lane = tid & 31, wrp = tid >> 5;
    const int byte_mode = (g_nonconform != 0u);

    __shared__ int2 q[QCAP];
    __shared__ int qn;
    __shared__ int ws[NWARP];
    __shared__ int s_excl;
    if (tid == 0) { qn = 0; s_excl = 0; }

    uint4 v[4];
    int cnt = load_count(mask, blk, tid, byte_mode, v);

    // warp inclusive scan of per-thread counts
    int incl = cnt;
#pragma unroll
    for (int o = 1; o < 32; o <<= 1) {
        int t = __shfl_up_sync(0xFFFFFFFFu, incl, o);
        if (lane >= o) incl += t;
    }
    if (lane == 31) ws[wrp] = incl;
    __syncthreads();

    int wbase = 0, total = 0;
#pragma unroll
    for (int i = 0; i < NWARP; i++) {
        int w = ws[i];
        wbase += (i < wrp) ? w : 0;
        total += w;
    }

    // Publish this block's status
    if (tid == 0) {
        if (blk == 0) {
            atomicExch(&g_desc[0], FLAG_PREFIX | (unsigned)total);
            if (blk == NBLK - 1) g_count = total;
        } else {
            atomicExch(&g_desc[blk], FLAG_AGG | (unsigned)total);
        }
    }

    // Warp 0 lookback: 32-descriptor window, atomicAdd polling (R6-proven).
    if (wrp == 0 && blk > 0) {
        int excl = 0;
        int k = blk - 1;
        while (true) {
            int idx = k - lane;
            unsigned s = (idx >= 0) ? atomicAdd(&g_desc[idx], 0u)
                                    : (FLAG_PREFIX | 0u);
            unsigned flag = s & 0xC0000000u;
            unsigned val  = s & VAL_MASK;
            unsigned bP = __ballot_sync(0xFFFFFFFFu, flag == FLAG_PREFIX);
            unsigned bI = __ballot_sync(0xFFFFFFFFu, flag == FLAG_INVALID);
            int firstP = bP ? (__ffs(bP) - 1) : 32;
            int firstI = bI ? (__ffs(bI) - 1) : 32;

            if (firstP < firstI) {
                unsigned contrib = (lane <= firstP) ? val : 0u;
#pragma unroll
                for (int o = 16; o; o >>= 1)
                    contrib += __shfl_xor_sync(0xFFFFFFFFu, contrib, o);
                excl += (int)contrib;
                break;
            } else if (firstI > 0) {
                unsigned contrib = (lane < firstI) ? val : 0u;
#pragma unroll
                for (int o = 16; o; o >>= 1)
                    contrib += __shfl_xor_sync(0xFFFFFFFFu, contrib, o);
                excl += (int)contrib;
                k -= firstI;
            } else {
                __nanosleep(60);
            }
        }
        if (lane == 0) {
            s_excl = excl;
            atomicExch(&g_desc[blk], FLAG_PREFIX | (unsigned)(excl + total));
            if (blk == NBLK - 1) g_count = excl + total;
        }
    }
    __syncthreads();

    int pout = s_excl + wbase + (incl - cnt);
    const int ebase = blk * ELEMS_PER_BLK + tid * ELEMS_PER_TH;

    // Emit ext row directly; enqueue (coord, pout) for cooperative copy.
    auto emit_one = [&](int elem) {
        if (pout < MAX_SELECTED) {
            int coord = elem % NUM_COORDS;
            int box   = elem / NUM_COORDS;
            int4 c = coords[coord];
            out_ext[pout] = make_float4((float)c.x, (float)c.y,
                                        (float)c.z, (float)box);
            int slot = atomicAdd(&qn, 1);
            if (slot < QCAP) {
                q[slot] = make_int2(coord, pout);
            } else {
                // overflow fallback (never hit at p=0.002): serial copy
                const float4* src = feat + (size_t)coord * 32;
                float4* dst = out_feat + (size_t)pout * 32;
                for (int t = 0; t < 32; t++) dst[t] = src[t];
            }
        }
        pout++;
    };

    if (byte_mode) {
        unsigned words[4] = { v[0].x, v[0].y, v[0].z, v[0].w };
#pragma unroll
        for (int j = 0; j < 4; j++) {
            unsigned w32 = words[j];
            if (w32 == 0u) continue;
#pragma unroll
            for (int b = 0; b < 4; b++)
                if ((w32 >> (8 * b)) & 0xFFu) emit_one(ebase + j * 4 + b);
        }
    } else {
#pragma unroll
        for (int i = 0; i < 4; i++) {
            unsigned words[4] = { v[i].x, v[i].y, v[i].z, v[i].w };
#pragma unroll
            for (int j = 0; j < 4; j++)
                if (words[j] != 0u) emit_one(ebase + i * 4 + j);
        }
    }
    __syncthreads();

    // Cooperative drain: one 512B feature row per warp per iteration.
    int nq = min(qn, QCAP);
    for (int t = wrp; t < nq; t += NWARP) {
        int2 e = q[t];
        out_feat[(size_t)e.y * 32 + lane] = feat[(size_t)e.x * 32 + lane];
    }
}

// ---------------------------------------------------------------------------
// Tail: zero rows [count, MAX_SELECTED) (ext + features), warp per row.
// Also resets g_desc for the next graph replay (stream-ordered after fused).
// ---------------------------------------------------------------------------
__global__ void k_tail(float4* __restrict__ out_ext,
                       float4* __restrict__ out_feat) {
    const int gt = blockIdx.x * blockDim.x + threadIdx.x;
    if (gt < NBLK) g_desc[gt] = FLAG_INVALID;

    const int gw   = gt >> 5;
    const int lane = threadIdx.x & 31;
    if (gw >= MAX_SELECTED || gw < g_count) return;
    out_feat[(size_t)gw * 32 + lane] = make_float4(0.f, 0.f, 0.f, 0.f);
    if (lane == 0) out_ext[gw] = make_float4(0.f, 0.f, 0.f, 0.f);
}

// ---------------------------------------------------------------------------
extern "C" void kernel_launch(void* const* d_in, const int* in_sizes, int n_in,
                              void* d_out, int out_size) {
    const int4*   coords = nullptr;
    const float4* feat   = nullptr;
    const void*   mask   = nullptr;
    for (int i = 0; i < n_in; i++) {
        if (in_sizes[i] == NUM_COORDS * 4)           coords = (const int4*)d_in[i];
        else if (in_sizes[i] == NUM_COORDS * FEAT_C) feat   = (const float4*)d_in[i];
        else if (in_sizes[i] == N_ELEMS)             mask   = d_in[i];
    }
    (void)out_size;

    float* out = (float*)d_out;
    float4* out_ext  = (float4*)out;                              // [262144,4] as floats
    float4* out_feat = (float4*)(out + 4 * (size_t)MAX_SELECTED); // [262144,128]

    k_detect<<<512, 256>>>((const unsigned*)mask);
    k_fused<<<NBLK, THREADS>>>(mask, coords, feat, out_ext, out_feat);
    k_tail<<<MAX_SELECTED * 32 / 256, 256>>>(out_ext, out_feat);
}

// round 13
// speedup vs baseline: 1.6709x; 1.6709x over previous
#include <cuda_runtime.h>
#include <stdint.h>

// Problem constants
#define NUM_COORDS   200000
#define FEAT_C       128
#define MAX_SELECTED 262144
#define N_ELEMS      (512 * NUM_COORDS)         // 102,400,000 mask elements
#define THREADS      512
#define ELEMS_PER_TH 16
#define ELEMS_PER_BLK (THREADS * ELEMS_PER_TH)  // 8192
#define NBLK         (N_ELEMS / ELEMS_PER_BLK)  // 12500 exactly
#define NWARP        (THREADS / 32)             // 16

// Scratch (device globals). All words are unconditionally overwritten every
// run -> no cross-replay state, no reset pass needed.
__device__ unsigned short g_bm[N_ELEMS / 16];   // 6.4M uint16 = 12.8 MB bitmask
__device__ int g_partials[NBLK];
__device__ int g_offsets[NBLK];
__device__ int g_count;
__device__ int g_selidx[MAX_SELECTED];
__device__ unsigned g_nonconform = 0;  // 1 => byte-bools; 0 => 32-bit elems

// ---------------------------------------------------------------------------
// Mode detection (256K-word scan). Word-mode masks contain only
// {0,1,0x3F800000}. Monotone + input-determined => replay-safe without reset.
// ---------------------------------------------------------------------------
__global__ void k_detect(const unsigned* __restrict__ w) {
    unsigned i = blockIdx.x * blockDim.x + threadIdx.x;
    unsigned bad = 0;
    for (unsigned j = i; j < (1u << 18); j += gridDim.x * blockDim.x) {
        unsigned v = w[j];
        if (v != 0u && v != 1u && v != 0x3F800000u) bad = 1u;
    }
    if (bad) g_nonconform = 1u;
}

// ---------------------------------------------------------------------------
// Pass 1: stream the 410 MB mask once; write 16-bit bitmask per thread
// (bit k = element ebase+k set) + per-block totals.
// ---------------------------------------------------------------------------
__global__ void __launch_bounds__(THREADS)
k_count(const void* __restrict__ mask) {
    const int blk = blockIdx.x, tid = threadIdx.x;
    const int lane = tid & 31, wrp = tid >> 5;
    const int byte_mode = (g_nonconform != 0u);

    unsigned m = 0;
    if (byte_mode) {
        uint4 v = ((const uint4*)mask)[(size_t)blk * THREADS + tid];  // 16 bytes
        unsigned words[4] = { v.x, v.y, v.z, v.w };
#pragma unroll
        for (int j = 0; j < 4; j++)
#pragma unroll
            for (int b = 0; b < 4; b++)
                if ((words[j] >> (8 * b)) & 0xFFu) m |= 1u << (j * 4 + b);
    } else {
        const uint4* p = (const uint4*)mask + (size_t)blk * (ELEMS_PER_BLK / 4)
                         + (size_t)tid * 4;
#pragma unroll
        for (int i = 0; i < 4; i++) {
            uint4 v = p[i];                                           // 16 words
            m |= (unsigned)(v.x != 0u) << (i * 4 + 0);
            m |= (unsigned)(v.y != 0u) << (i * 4 + 1);
            m |= (unsigned)(v.z != 0u) << (i * 4 + 2);
            m |= (unsigned)(v.w != 0u) << (i * 4 + 3);
        }
    }
    g_bm[(size_t)blk * THREADS + tid] = (unsigned short)m;  // coalesced 2B/thread

    // block total
    int s = __popc(m);
#pragma unroll
    for (int o = 16; o; o >>= 1) s += __shfl_down_sync(0xFFFFFFFFu, s, o);
    __shared__ int ws[NWARP];
    if (lane == 0) ws[wrp] = s;
    __syncthreads();
    if (tid < NWARP) {
        int t = ws[tid];
#pragma unroll
        for (int o = NWARP / 2; o; o >>= 1) t += __shfl_down_sync(0xFFFFu, t, o);
        if (tid == 0) g_partials[blk] = t;
    }
}

// ---------------------------------------------------------------------------
// Pass 2: single-block exclusive scan of 12500 partials (serial-per-thread
// chunks of 13 + one block scan) -> g_offsets, g_count. ~4 us.
// ---------------------------------------------------------------------------
#define SCHUNK 13   // 13 * 1024 = 13312 >= 12500
__global__ void __launch_bounds__(1024)
k_scan() {
    const int tid = threadIdx.x;
    const int lane = tid & 31, wrp = tid >> 5;
    const int base = tid * SCHUNK;

    int loc[SCHUNK];
    int s = 0;
#pragma unroll
    for (int j = 0; j < SCHUNK; j++) {
        int i = base + j;
        int v = (i < NBLK) ? g_partials[i] : 0;
        loc[j] = s;               // exclusive within thread
        s += v;
    }

    // block scan of per-thread sums (1024 threads = 32 warps)
    int incl = s;
#pragma unroll
    for (int o = 1; o < 32; o <<= 1) {
        int t = __shfl_up_sync(0xFFFFFFFFu, incl, o);
        if (lane >= o) incl += t;
    }
    __shared__ int wsum[32];
    if (lane == 31) wsum[wrp] = incl;
    __syncthreads();

    int wb = 0, total = 0;
#pragma unroll
    for (int i = 0; i < 32; i++) {
        int w = wsum[i];
        wb += (i < wrp) ? w : 0;
        total += w;
    }
    int excl = wb + (incl - s);   // exclusive prefix of this thread's chunk

#pragma unroll
    for (int j = 0; j < SCHUNK; j++) {
        int i = base + j;
        if (i < NBLK) g_offsets[i] = excl + loc[j];
    }
    if (tid == 0) g_count = total;
}

// ---------------------------------------------------------------------------
// Pass 3: emit from the 12.8 MB bitmask (mode-independent). No atomics,
// no lookback — offsets precomputed. Writes ext rows + selidx.
// ---------------------------------------------------------------------------
__global__ void __launch_bounds__(THREADS)
k_emit(const int4* __restrict__ coords,
       float4* __restrict__ out_ext) {
    const int blk = blockIdx.x, tid = threadIdx.x;
    const int lane = tid & 31, wrp = tid >> 5;

    unsigned m = g_bm[(size_t)blk * THREADS + tid];
    int cnt = __popc(m);

    int incl = cnt;
#pragma unroll
    for (int o = 1; o < 32; o <<= 1) {
        int t = __shfl_up_sync(0xFFFFFFFFu, incl, o);
        if (lane >= o) incl += t;
    }
    __shared__ int ws[NWARP];
    if (lane == 31) ws[wrp] = incl;
    __syncthreads();
    int wbase = 0;
#pragma unroll
    for (int i = 0; i < NWARP; i++) wbase += (i < wrp) ? ws[i] : 0;

    int pout = g_offsets[blk] + wbase + (incl - cnt);
    const int ebase = blk * ELEMS_PER_BLK + tid * ELEMS_PER_TH;

    while (m) {
        int b = __ffs(m) - 1;
        m &= m - 1;
        if (pout < MAX_SELECTED) {
            int elem  = ebase + b;
            int coord = elem % NUM_COORDS;
            int box   = elem / NUM_COORDS;
            g_selidx[pout] = coord;
            int4 c = coords[coord];
            out_ext[pout] = make_float4((float)c.x, (float)c.y,
                                        (float)c.z, (float)box);
        }
        pout++;
    }
}

// ---------------------------------------------------------------------------
// Pass 4: warp-per-row feature gather + zero tail (proven 39.6 us kernel).
// ---------------------------------------------------------------------------
__global__ void k_gather(const float4* __restrict__ feat,
                         float4* __restrict__ out_ext,
                         float4* __restrict__ out_feat) {
    const int gw   = (int)((blockIdx.x * (unsigned)blockDim.x + threadIdx.x) >> 5);
    const int lane = threadIdx.x & 31;
    if (gw >= MAX_SELECTED) return;
    if (gw < g_count) {
        int c = g_selidx[gw];
        out_feat[(size_t)gw * 32 + lane] = feat[(size_t)c * 32 + lane];
    } else {
        out_feat[(size_t)gw * 32 + lane] = make_float4(0.f, 0.f, 0.f, 0.f);
        if (lane == 0) out_ext[gw] = make_float4(0.f, 0.f, 0.f, 0.f);
    }
}

// ---------------------------------------------------------------------------
extern "C" void kernel_launch(void* const* d_in, const int* in_sizes, int n_in,
                              void* d_out, int out_size) {
    const int4*   coords = nullptr;
    const float4* feat   = nullptr;
    const void*   mask   = nullptr;
    for (int i = 0; i < n_in; i++) {
        if (in_sizes[i] == NUM_COORDS * 4)           coords = (const int4*)d_in[i];
        else if (in_sizes[i] == NUM_COORDS * FEAT_C) feat   = (const float4*)d_in[i];
        else if (in_sizes[i] == N_ELEMS)             mask   = d_in[i];
    }
    (void)out_size;

    float* out = (float*)d_out;
    float4* out_ext  = (float4*)out;                              // [262144,4] as floats
    float4* out_feat = (float4*)(out + 4 * (size_t)MAX_SELECTED); // [262144,128]

    k_detect<<<512, 256>>>((const unsigned*)mask);
    k_count<<<NBLK, THREADS>>>(mask);
    k_scan<<<1, 1024>>>();
    k_emit<<<NBLK, THREADS>>>(coords, out_ext);
    k_gather<<<MAX_SELECTED * 32 / 256, 256>>>(feat, out_ext, out_feat);
}

// round 14
// speedup vs baseline: 1.7414x; 1.0422x over previous
#include <cuda_runtime.h>
#include <stdint.h>

// Problem constants
#define NUM_COORDS   200000
#define FEAT_C       128
#define MAX_SELECTED 262144
#define N_ELEMS      (512 * NUM_COORDS)         // 102,400,000 mask elements
#define THREADS      512
#define ELEMS_PER_TH 32
#define ELEMS_PER_BLK (THREADS * ELEMS_PER_TH)  // 16384
#define NBLK         (N_ELEMS / ELEMS_PER_BLK)  // 6250 exactly
#define NWARP        (THREADS / 32)             // 16
#define NWORDS       (N_ELEMS / 32)             // 3.2M uint32 bitmask words

// Scratch (device globals). All words unconditionally overwritten every run
// -> no cross-replay state, no reset pass needed.
__device__ unsigned g_bm32[NWORDS];             // 12.8 MB bitmask
__device__ int g_partials[NBLK];
__device__ int g_offsets[NBLK];
__device__ int g_count;
__device__ int g_selidx[MAX_SELECTED];
__device__ unsigned g_nonconform = 0;  // 1 => byte-bools; 0 => 32-bit elems

// ---------------------------------------------------------------------------
// Mode detection (256K-word scan). Word-mode masks contain only
// {0,1,0x3F800000}. Monotone + input-determined => replay-safe without reset.
// ---------------------------------------------------------------------------
__global__ void k_detect(const unsigned* __restrict__ w) {
    unsigned i = blockIdx.x * blockDim.x + threadIdx.x;
    unsigned bad = 0;
    for (unsigned j = i; j < (1u << 18); j += gridDim.x * blockDim.x) {
        unsigned v = w[j];
        if (v != 0u && v != 1u && v != 0x3F800000u) bad = 1u;
    }
    if (bad) g_nonconform = 1u;
}

// ---------------------------------------------------------------------------
// Pass 1: stream the 410 MB mask once; each thread produces one uint32
// bitmask word (32 elements) + per-block totals.
// ---------------------------------------------------------------------------
__global__ void __launch_bounds__(THREADS)
k_count(const void* __restrict__ mask) {
    const int blk = blockIdx.x, tid = threadIdx.x;
    const int lane = tid & 31, wrp = tid >> 5;
    const int byte_mode = (g_nonconform != 0u);

    unsigned m = 0;
    if (byte_mode) {
        // 32 bytes = 2 x uint4
        const uint4* p = (const uint4*)mask + (size_t)blk * (THREADS * 2)
                         + (size_t)tid * 2;
#pragma unroll
        for (int i = 0; i < 2; i++) {
            uint4 v = p[i];
            unsigned words[4] = { v.x, v.y, v.z, v.w };
#pragma unroll
            for (int j = 0; j < 4; j++)
#pragma unroll
                for (int b = 0; b < 4; b++)
                    if ((words[j] >> (8 * b)) & 0xFFu)
                        m |= 1u << (i * 16 + j * 4 + b);
        }
    } else {
        // 32 words = 8 x uint4 (high MLP streaming)
        const uint4* p = (const uint4*)mask + (size_t)blk * (ELEMS_PER_BLK / 4)
                         + (size_t)tid * 8;
#pragma unroll
        for (int i = 0; i < 8; i++) {
            uint4 v = p[i];
            m |= (unsigned)(v.x != 0u) << (i * 4 + 0);
            m |= (unsigned)(v.y != 0u) << (i * 4 + 1);
            m |= (unsigned)(v.z != 0u) << (i * 4 + 2);
            m |= (unsigned)(v.w != 0u) << (i * 4 + 3);
        }
    }
    g_bm32[(size_t)blk * THREADS + tid] = m;    // coalesced 4B/thread

    // block total
    int s = __popc(m);
#pragma unroll
    for (int o = 16; o; o >>= 1) s += __shfl_down_sync(0xFFFFFFFFu, s, o);
    __shared__ int ws[NWARP];
    if (lane == 0) ws[wrp] = s;
    __syncthreads();
    if (tid < NWARP) {
        int t = ws[tid];
#pragma unroll
        for (int o = NWARP / 2; o; o >>= 1) t += __shfl_down_sync(0xFFFFu, t, o);
        if (tid == 0) g_partials[blk] = t;
    }
}

// ---------------------------------------------------------------------------
// Pass 2: single-block exclusive scan of 6250 partials (serial chunks of 7 +
// one block scan). ~3 us.
// ---------------------------------------------------------------------------
#define SCHUNK 7   // 7 * 1024 = 7168 >= 6250
__global__ void __launch_bounds__(1024)
k_scan() {
    const int tid = threadIdx.x;
    const int lane = tid & 31, wrp = tid >> 5;
    const int base = tid * SCHUNK;

    int loc[SCHUNK];
    int s = 0;
#pragma unroll
    for (int j = 0; j < SCHUNK; j++) {
        int i = base + j;
        int v = (i < NBLK) ? g_partials[i] : 0;
        loc[j] = s;
        s += v;
    }

    int incl = s;
#pragma unroll
    for (int o = 1; o < 32; o <<= 1) {
        int t = __shfl_up_sync(0xFFFFFFFFu, incl, o);
        if (lane >= o) incl += t;
    }
    __shared__ int wsum[32];
    if (lane == 31) wsum[wrp] = incl;
    __syncthreads();

    int wb = 0, total = 0;
#pragma unroll
    for (int i = 0; i < 32; i++) {
        int w = wsum[i];
        wb += (i < wrp) ? w : 0;
        total += w;
    }
    int excl = wb + (incl - s);

#pragma unroll
    for (int j = 0; j < SCHUNK; j++) {
        int i = base + j;
        if (i < NBLK) g_offsets[i] = excl + loc[j];
    }
    if (tid == 0) g_count = total;
}

// ---------------------------------------------------------------------------
// Pass 3: emit from the bitmask — one uint32 word (32 elements) per thread.
// No atomics, offsets precomputed. Writes ext rows + selidx.
// ---------------------------------------------------------------------------
__global__ void __launch_bounds__(THREADS)
k_emit(const int4* __restrict__ coords,
       float4* __restrict__ out_ext) {
    const int blk = blockIdx.x, tid = threadIdx.x;
    const int lane = tid & 31, wrp = tid >> 5;

    const int widx = blk * THREADS + tid;
    unsigned m = g_bm32[widx];
    int cnt = __popc(m);

    int incl = cnt;
#pragma unroll
    for (int o = 1; o < 32; o <<= 1) {
        int t = __shfl_up_sync(0xFFFFFFFFu, incl, o);
        if (lane >= o) incl += t;
    }
    __shared__ int ws[NWARP];
    if (lane == 31) ws[wrp] = incl;
    __syncthreads();
    int wbase = 0;
#pragma unroll
    for (int i = 0; i < NWARP; i++) wbase += (i < wrp) ? ws[i] : 0;

    int pout = g_offsets[blk] + wbase + (incl - cnt);
    const int ebase = widx * 32;

    while (m) {
        int b = __ffs(m) - 1;
        m &= m - 1;
        if (pout < MAX_SELECTED) {
            int elem  = ebase + b;
            int coord = elem % NUM_COORDS;
            int box   = elem / NUM_COORDS;
            g_selidx[pout] = coord;
            int4 c = coords[coord];
            out_ext[pout] = make_float4((float)c.x, (float)c.y,
                                        (float)c.z, (float)box);
        }
        pout++;
    }
}

// ---------------------------------------------------------------------------
// Pass 4: feature gather — 8 rows per warp, loads batched before stores
// (MLP=8) + zero tail. Block 256 = 8 warps = 64 rows; grid 4096.
// ---------------------------------------------------------------------------
#define GROWS 8
__global__ void __launch_bounds__(256)
k_gather(const float4* __restrict__ feat,
         float4* __restrict__ out_ext,
         float4* __restrict__ out_feat) {
    const int wrp  = (int)threadIdx.x >> 5;
    const int lane = (int)threadIdx.x & 31;
    const int rbase = (blockIdx.x * 8 + wrp) * GROWS;   // 8 warps/block
    const int count = g_count;

    int cs[GROWS];
#pragma unroll
    for (int j = 0; j < GROWS; j++) {
        int row = rbase + j;
        cs[j] = (row < count) ? g_selidx[row] : -1;
    }

    float4 r[GROWS];
#pragma unroll
    for (int j = 0; j < GROWS; j++) {
        r[j] = (cs[j] >= 0) ? feat[(size_t)cs[j] * 32 + lane]
                            : make_float4(0.f, 0.f, 0.f, 0.f);
    }
#pragma unroll
    for (int j = 0; j < GROWS; j++) {
        int row = rbase + j;
        out_feat[(size_t)row * 32 + lane] = r[j];
        if (cs[j] < 0 && lane == 0)
            out_ext[row] = make_float4(0.f, 0.f, 0.f, 0.f);
    }
}

// ---------------------------------------------------------------------------
extern "C" void kernel_launch(void* const* d_in, const int* in_sizes, int n_in,
                              void* d_out, int out_size) {
    const int4*   coords = nullptr;
    const float4* feat   = nullptr;
    const void*   mask   = nullptr;
    for (int i = 0; i < n_in; i++) {
        if (in_sizes[i] == NUM_COORDS * 4)           coords = (const int4*)d_in[i];
        else if (in_sizes[i] == NUM_COORDS * FEAT_C) feat   = (const float4*)d_in[i];
        else if (in_sizes[i] == N_ELEMS)             mask   = d_in[i];
    }
    (void)out_size;

    float* out = (float*)d_out;
    float4* out_ext  = (float4*)out;                              // [262144,4] as floats
    float4* out_feat = (float4*)(out + 4 * (size_t)MAX_SELECTED); // [262144,128]

    k_detect<<<512, 256>>>((const unsigned*)mask);
    k_count<<<NBLK, THREADS>>>(mask);
    k_scan<<<1, 1024>>>();
    k_emit<<<NBLK, THREADS>>>(coords, out_ext);
    k_gather<<<MAX_SELECTED / (8 * GROWS), 256>>>(feat, out_ext, out_feat);
}